// round 5
// baseline (speedup 1.0000x reference)
#include <cuda_runtime.h>

// Problem constants (fixed by setup_inputs: B=2, Lq=16384, D=1024, M=64, H=16)
#define DMODEL 1024
#define ROWS   128            // B*M flattened rows
#define TPF    256            // Lq / M  (tokens per frame)

// GEMM tiling
#define BN     128            // cols per block
#define BK     64             // K per block (split-K chunk)
#define KCH    16             // K per smem stage
#define KSPLIT 16             // split-K factor (grid.y)
#define NTILE  (DMODEL / BN)  // 8 column tiles

// Scratch (static __device__ arrays — no runtime allocation)
__device__ float g_P[KSPLIT * ROWS * DMODEL];  // split-K partials (8 MB)
__device__ float g_V[ROWS * DMODEL];           // v = context @ Wkv_v + bkv_v

// ---------------------------------------------------------------------------
// Packed fp32 helpers (Blackwell FFMA2 via PTX fma.rn.f32x2)
// ---------------------------------------------------------------------------
typedef unsigned long long u64;

__device__ __forceinline__ u64 pack2_dup(float v) {
    u64 r;
    asm("mov.b64 %0, {%1, %1};" : "=l"(r) : "f"(v));
    return r;
}
__device__ __forceinline__ u64 fma2(u64 a, u64 b, u64 c) {
    u64 d;
    asm("fma.rn.f32x2 %0, %1, %2, %3;" : "=l"(d) : "l"(a), "l"(b), "l"(c));
    return d;
}
__device__ __forceinline__ void unpack2(u64 v, float& lo, float& hi) {
    asm("mov.b64 {%0, %1}, %2;" : "=f"(lo), "=f"(hi) : "l"(v));
}

// ---------------------------------------------------------------------------
// Split-K fp32 GEMM: P[ks] = Atile @ Wtile (partial over k-slice).
// A is [128 x 1024] row-major (context flattened, or g_V when A_in==nullptr).
// W accessed as W[k*ldw + woff + j].
// Block tile 128x128, thread tile 8x8 (packed f32x2 accumulators), 256 threads.
// ---------------------------------------------------------------------------
__global__ __launch_bounds__(256, 1)
void gemm_partial(const float* __restrict__ A_in,
                  const float* __restrict__ W,
                  int ldw, int woff)
{
    __shared__ float a_s[KCH][ROWS + 4];   // stored transposed: a_s[k][row]
    __shared__ float w_s[KCH][BN + 4];     // w_s[k][col]

    const float* A = A_in ? A_in : g_V;

    const int tid = threadIdx.x;
    const int j0  = blockIdx.x * BN;
    const int k0  = blockIdx.y * BK;

    // A loader: thread -> (row ar, 8 consecutive k at offset ak)
    const int ar = tid >> 1;
    const int ak = (tid & 1) * 8;
    // W loader: thread -> rows wk and wk+8, 4 consecutive cols at wc
    const int wk = tid >> 5;
    const int wc = (tid & 31) * 4;

    // Compute mapping: 16x16 thread grid, 8 rows x 8 cols each
    const int ty = tid >> 4;
    const int tx = tid & 15;

    float4 aR0, aR1, wR0, wR1;

    // Prefetch stage 0
    {
        const float* ap = A + ar * DMODEL + k0 + ak;
        aR0 = *(const float4*)(ap);
        aR1 = *(const float4*)(ap + 4);
        const float* wp = W + (size_t)(k0 + wk) * ldw + woff + j0 + wc;
        wR0 = *(const float4*)(wp);
        wR1 = *(const float4*)(wp + (size_t)8 * ldw);
    }

    // Packed accumulators: acc2[i][j] holds columns (2j, 2j+1) of row i
    u64 acc2[8][4];
#pragma unroll
    for (int i = 0; i < 8; i++)
#pragma unroll
        for (int j = 0; j < 4; j++) acc2[i][j] = 0ull;

#pragma unroll
    for (int c = 0; c < BK / KCH; c++) {
        // Stage registers -> smem
        a_s[ak + 0][ar] = aR0.x;
        a_s[ak + 1][ar] = aR0.y;
        a_s[ak + 2][ar] = aR0.z;
        a_s[ak + 3][ar] = aR0.w;
        a_s[ak + 4][ar] = aR1.x;
        a_s[ak + 5][ar] = aR1.y;
        a_s[ak + 6][ar] = aR1.z;
        a_s[ak + 7][ar] = aR1.w;
        *(float4*)&w_s[wk][wc]     = wR0;
        *(float4*)&w_s[wk + 8][wc] = wR1;
        __syncthreads();

        // Prefetch next stage (global -> registers, overlaps compute)
        if (c < BK / KCH - 1) {
            const int kn = k0 + (c + 1) * KCH;
            const float* ap = A + ar * DMODEL + kn + ak;
            aR0 = *(const float4*)(ap);
            aR1 = *(const float4*)(ap + 4);
            const float* wp = W + (size_t)(kn + wk) * ldw + woff + j0 + wc;
            wR0 = *(const float4*)(wp);
            wR1 = *(const float4*)(wp + (size_t)8 * ldw);
        }

#pragma unroll
        for (int k = 0; k < KCH; k++) {
            float af[8];
            u64   w2[4];
            *(float4*)&af[0] = *(const float4*)&a_s[k][ty * 8];
            *(float4*)&af[4] = *(const float4*)&a_s[k][ty * 8 + 4];
            // w pairs: columns (tx*8 + 2j, tx*8 + 2j + 1), read as 2x float4 = 4x u64
            *(float4*)&w2[0] = *(const float4*)&w_s[k][tx * 8];
            *(float4*)&w2[2] = *(const float4*)&w_s[k][tx * 8 + 4];
#pragma unroll
            for (int i = 0; i < 8; i++) {
                const u64 a2 = pack2_dup(af[i]);
#pragma unroll
                for (int j = 0; j < 4; j++)
                    acc2[i][j] = fma2(a2, w2[j], acc2[i][j]);
            }
        }
        __syncthreads();
    }

    // Write split-K partial tile
    float* pbase = g_P + (size_t)blockIdx.y * (ROWS * DMODEL) + (size_t)j0;
#pragma unroll
    for (int i = 0; i < 8; i++) {
        float r[8];
#pragma unroll
        for (int j = 0; j < 4; j++) unpack2(acc2[i][j], r[2 * j], r[2 * j + 1]);
        float* pr = pbase + (size_t)(ty * 8 + i) * DMODEL + tx * 8;
        *(float4*)(pr)     = *(float4*)&r[0];
        *(float4*)(pr + 4) = *(float4*)&r[4];
    }
}

// ---------------------------------------------------------------------------
// Stage-1 split-K reduction + bias -> g_V.
// 4 threads per float4 element (4 partials each) + smem combine.
// Deterministic: fixed order ((g0+g1)+g2)+g3, each g = sequential sum of 4.
// ---------------------------------------------------------------------------
__global__ __launch_bounds__(256)
void reduce_v(const float* __restrict__ bkv)
{
    __shared__ float4 red[64][4];

    const int tid = threadIdx.x;
    const int pg  = tid & 3;        // partial group 0..3
    const int el  = tid >> 2;       // local element 0..63
    const int idx = blockIdx.x * 64 + el;   // float4 index into [ROWS*DMODEL/4)

    const float* pp = g_P + (size_t)pg * 4 * ROWS * DMODEL;
    float4 s = make_float4(0.f, 0.f, 0.f, 0.f);
#pragma unroll
    for (int p = 0; p < 4; p++) {
        const float4 v = ((const float4*)(pp + (size_t)p * ROWS * DMODEL))[idx];
        s.x += v.x; s.y += v.y; s.z += v.z; s.w += v.w;
    }
    red[el][pg] = s;
    __syncthreads();

    if (pg == 0) {
        const int col = (idx & (DMODEL / 4 - 1)) * 4;
        const float* bp = bkv + DMODEL + col;
        float4 acc = make_float4(__ldg(bp), __ldg(bp + 1), __ldg(bp + 2), __ldg(bp + 3));
#pragma unroll
        for (int q = 0; q < 4; q++) {
            const float4 v = red[el][q];
            acc.x += v.x; acc.y += v.y; acc.z += v.z; acc.w += v.w;
        }
        ((float4*)g_V)[idx] = acc;
    }
}

// ---------------------------------------------------------------------------
// Fused stage-2 reduce + bias + broadcast.
// Block (g, rc): reduce 16 partials for row g (redundantly per rc — L2-resident,
// hidden under DRAM writes), then stream 64 identical output rows.
// out[b, l, :] = z[b*64 + (l>>8), :]
// ---------------------------------------------------------------------------
__global__ __launch_bounds__(256)
void reduce_broadcast(const float* __restrict__ bo, float* __restrict__ out)
{
    const int g   = blockIdx.x;     // 0..127 : (b*64 + m)
    const int rc  = blockIdx.y;     // 0..3   : 64-row chunk
    const int t   = threadIdx.x;    // float4 column 0..255
    const int idx = g * (DMODEL / 4) + t;

    const float* bp = bo + t * 4;
    float4 s = make_float4(__ldg(bp), __ldg(bp + 1), __ldg(bp + 2), __ldg(bp + 3));

    const float4* pp = (const float4*)g_P + idx;
#pragma unroll
    for (int p = 0; p < KSPLIT; p++) {
        const float4 v = pp[(size_t)p * (ROWS * DMODEL / 4)];
        s.x += v.x; s.y += v.y; s.z += v.z; s.w += v.w;
    }

    float4* op = (float4*)out + ((size_t)g * TPF + (size_t)rc * 64) * (DMODEL / 4) + t;
#pragma unroll
    for (int r = 0; r < 64; r++)
        op[(size_t)r * (DMODEL / 4)] = s;
}

// ---------------------------------------------------------------------------
// Inputs (metadata order): 0:x 1:context 2:Wq 3:bq 4:Wkv 5:bkv 6:Wo 7:bo
// x, Wq, bq are DEAD in the reference (q is never used).
// ---------------------------------------------------------------------------
extern "C" void kernel_launch(void* const* d_in, const int* in_sizes, int n_in,
                              void* d_out, int out_size)
{
    (void)in_sizes; (void)n_in; (void)out_size;

    const float* context = (const float*)d_in[1];
    const float* Wkv     = (const float*)d_in[4];
    const float* bkv     = (const float*)d_in[5];
    const float* Wo      = (const float*)d_in[6];
    const float* bo      = (const float*)d_in[7];
    float* out           = (float*)d_out;

    dim3 ggrid(NTILE, KSPLIT);

    // Stage 1: v = context @ Wkv[:, 1024:2048] + bkv[1024:]
    gemm_partial<<<ggrid, 256>>>(context, Wkv, 2 * DMODEL, DMODEL);
    reduce_v<<<ROWS * DMODEL / 4 / 64, 256>>>(bkv);

    // Stage 2: z-partials = v @ Wo
    gemm_partial<<<ggrid, 256>>>(nullptr, Wo, DMODEL, 0);

    // Stage 3: fused reduce + bias + broadcast to the 134 MB output
    reduce_broadcast<<<dim3(ROWS, TPF / 64), 256>>>(bo, out);
}

// round 8
// speedup vs baseline: 1.0673x; 1.0673x over previous
#include <cuda_runtime.h>
#include <cstdint>

// Problem constants (fixed by setup_inputs: B=2, Lq=16384, D=1024, M=64, H=16)
#define DMODEL 1024
#define ROWS   128            // B*M flattened rows
#define TPF    256            // Lq / M  (tokens per frame)

#define KSPLIT 16             // split-K factor (grid.y)
#define BK     64             // K per block
#define BN     128            // cols per block
#define NTILE  (DMODEL / BN)  // 8 column tiles

// Scratch (static __device__ arrays — no runtime allocation)
__device__ float g_P[KSPLIT * ROWS * DMODEL];  // split-K partials (8 MB)
__device__ float g_V[ROWS * DMODEL];           // v = context @ Wkv_v + bkv_v

// ---------------------------------------------------------------------------
// tf32 helpers (mma.sync — baseline PTX, works at compute_100)
// ---------------------------------------------------------------------------
__device__ __forceinline__ uint32_t f2tf32(float f) {
    uint32_t r;
    asm("cvt.rna.tf32.f32 %0, %1;" : "=r"(r) : "f"(f));
    return r;
}
__device__ __forceinline__ void cvt_hilo(float f, uint32_t& hi, uint32_t& lo) {
    hi = f2tf32(f);
    lo = f2tf32(f - __uint_as_float(hi));
}
__device__ __forceinline__ void mma_tf32(float* d, const uint32_t* a, const uint32_t* b) {
    asm volatile(
        "mma.sync.aligned.m16n8k8.row.col.f32.tf32.tf32.f32 "
        "{%0,%1,%2,%3}, {%4,%5,%6,%7}, {%8,%9}, {%0,%1,%2,%3};"
        : "+f"(d[0]), "+f"(d[1]), "+f"(d[2]), "+f"(d[3])
        : "r"(a[0]), "r"(a[1]), "r"(a[2]), "r"(a[3]), "r"(b[0]), "r"(b[1]));
}

// ---------------------------------------------------------------------------
// SMEM layout (dynamic):
//  a_hi/a_lo: [128 m][68 k]  (stride 68 floats = 272 B, 16B-aligned rows,
//             fragment pattern (4g+r) mod 32 -> conflict-free)
//  b_hi/b_lo: [64 k][132 n]  (stride 132 floats = 528 B)
// ---------------------------------------------------------------------------
#define A_LD 68
#define B_LD 132
#define SM_AH 0
#define SM_AL (SM_AH + ROWS * A_LD * 4)            // 34816
#define SM_BH (SM_AL + ROWS * A_LD * 4)            // 69632
#define SM_BL (SM_BH + BK * B_LD * 4)              // 103424
#define SMEM_TOTAL (SM_BL + BK * B_LD * 4)         // 137216

// ---------------------------------------------------------------------------
// Split-K tf32 tensor-core GEMM:
//   g_P[ks][0:128][j0:j0+128] = A[:, k-slice] @ W[k-slice, j0:j0+128]
// A = context (row-major [128 x 1024]) or g_V when A_in == nullptr.
// W accessed as W[k*ldw + woff + j].
// 256 threads = 8 warps as 4(M) x 2(N); warp tile 32 x 64.
// 3-pass tf32 hi/lo for fp32-grade accuracy.
// ---------------------------------------------------------------------------
__global__ __launch_bounds__(256, 1)
void gemm_tc(const float* __restrict__ A_in,
             const float* __restrict__ W,
             int ldw, int woff)
{
    extern __shared__ char sm[];
    float* a_hi = (float*)(sm + SM_AH);
    float* a_lo = (float*)(sm + SM_AL);
    float* b_hi = (float*)(sm + SM_BH);
    float* b_lo = (float*)(sm + SM_BL);

    const float* A = A_in ? A_in : g_V;
    const int tid = threadIdx.x;
    const int wid = tid >> 5;
    const int lane = tid & 31;
    const int j0 = blockIdx.x * BN;
    const int k0 = blockIdx.y * BK;

    // --- Stage A tile [128 m][64 k] as tf32 hi/lo ---
    {
        const int row = tid >> 1;
        const int kb  = (tid & 1) * 32;
        const float* ap = A + (size_t)row * DMODEL + k0 + kb;
        float* dh = a_hi + row * A_LD + kb;
        float* dl = a_lo + row * A_LD + kb;
#pragma unroll
        for (int c = 0; c < 8; c++) {
            float4 f = *(const float4*)(ap + c * 4);
            uint32_t h[4], l[4];
            cvt_hilo(f.x, h[0], l[0]);
            cvt_hilo(f.y, h[1], l[1]);
            cvt_hilo(f.z, h[2], l[2]);
            cvt_hilo(f.w, h[3], l[3]);
            *(uint4*)(dh + c * 4) = make_uint4(h[0], h[1], h[2], h[3]);
            *(uint4*)(dl + c * 4) = make_uint4(l[0], l[1], l[2], l[3]);
        }
    }

    // --- Stage W tile [64 k][128 n] as tf32 hi/lo (coalesced) ---
    {
        const int kl = tid >> 5;          // 0..7, step 8
        const int n  = (tid & 31) * 4;
#pragma unroll
        for (int it = 0; it < 8; it++) {
            const int k = it * 8 + kl;
            float4 f = *(const float4*)(W + (size_t)(k0 + k) * ldw + woff + j0 + n);
            uint32_t h[4], l[4];
            cvt_hilo(f.x, h[0], l[0]);
            cvt_hilo(f.y, h[1], l[1]);
            cvt_hilo(f.z, h[2], l[2]);
            cvt_hilo(f.w, h[3], l[3]);
            *(uint4*)(b_hi + k * B_LD + n) = make_uint4(h[0], h[1], h[2], h[3]);
            *(uint4*)(b_lo + k * B_LD + n) = make_uint4(l[0], l[1], l[2], l[3]);
        }
    }
    __syncthreads();

    // --- Compute: warp (m0, n0); 2 m-tiles x 8 n-tiles of m16n8k8 ---
    const int m0 = (wid >> 1) * 32;
    const int n0 = (wid & 1) * 64;
    const int g  = lane >> 2;        // 0..7
    const int r  = lane & 3;         // 0..3

    float acc[2][8][4];
#pragma unroll
    for (int mt = 0; mt < 2; mt++)
#pragma unroll
        for (int nt = 0; nt < 8; nt++)
#pragma unroll
            for (int i = 0; i < 4; i++) acc[mt][nt][i] = 0.0f;

    const uint32_t* ah_s = (const uint32_t*)a_hi;
    const uint32_t* al_s = (const uint32_t*)a_lo;
    const uint32_t* bh_s = (const uint32_t*)b_hi;
    const uint32_t* bl_s = (const uint32_t*)b_lo;

#pragma unroll
    for (int ks = 0; ks < 8; ks++) {
        const int kk = ks * 8 + r;
        // A fragments for both m-tiles, hi and lo
        uint32_t ah[2][4], al[2][4];
#pragma unroll
        for (int mt = 0; mt < 2; mt++) {
            const int mrow = m0 + mt * 16 + g;
            ah[mt][0] = ah_s[mrow * A_LD + kk];
            ah[mt][1] = ah_s[(mrow + 8) * A_LD + kk];
            ah[mt][2] = ah_s[mrow * A_LD + kk + 4];
            ah[mt][3] = ah_s[(mrow + 8) * A_LD + kk + 4];
            al[mt][0] = al_s[mrow * A_LD + kk];
            al[mt][1] = al_s[(mrow + 8) * A_LD + kk];
            al[mt][2] = al_s[mrow * A_LD + kk + 4];
            al[mt][3] = al_s[(mrow + 8) * A_LD + kk + 4];
        }
#pragma unroll
        for (int nt = 0; nt < 8; nt++) {
            const int ncol = n0 + nt * 8 + g;
            uint32_t bh[2], bl[2];
            bh[0] = bh_s[(ks * 8 + r) * B_LD + ncol];
            bh[1] = bh_s[(ks * 8 + r + 4) * B_LD + ncol];
            bl[0] = bl_s[(ks * 8 + r) * B_LD + ncol];
            bl[1] = bl_s[(ks * 8 + r + 4) * B_LD + ncol];
#pragma unroll
            for (int mt = 0; mt < 2; mt++) {
                mma_tf32(acc[mt][nt], ah[mt], bh);   // hi*hi
                mma_tf32(acc[mt][nt], ah[mt], bl);   // hi*lo
                mma_tf32(acc[mt][nt], al[mt], bh);   // lo*hi
            }
        }
    }

    // --- Epilogue: write warp tile to g_P ---
    float* pbase = g_P + (size_t)blockIdx.y * (ROWS * DMODEL) + j0;
#pragma unroll
    for (int mt = 0; mt < 2; mt++) {
        const int mrow = m0 + mt * 16 + g;
#pragma unroll
        for (int nt = 0; nt < 8; nt++) {
            const int ncol = n0 + nt * 8 + 2 * r;
            *(float2*)(pbase + (size_t)mrow * DMODEL + ncol) =
                make_float2(acc[mt][nt][0], acc[mt][nt][1]);
            *(float2*)(pbase + (size_t)(mrow + 8) * DMODEL + ncol) =
                make_float2(acc[mt][nt][2], acc[mt][nt][3]);
        }
    }
}

// ---------------------------------------------------------------------------
// Stage-1 split-K reduction + bias -> g_V (deterministic fixed order).
// ---------------------------------------------------------------------------
__global__ __launch_bounds__(256)
void reduce_v(const float* __restrict__ bkv)
{
    __shared__ float4 red[64][4];

    const int tid = threadIdx.x;
    const int pg  = tid & 3;
    const int el  = tid >> 2;
    const int idx = blockIdx.x * 64 + el;

    const float* pp = g_P + (size_t)pg * 4 * ROWS * DMODEL;
    float4 s = make_float4(0.f, 0.f, 0.f, 0.f);
#pragma unroll
    for (int p = 0; p < 4; p++) {
        const float4 v = ((const float4*)(pp + (size_t)p * ROWS * DMODEL))[idx];
        s.x += v.x; s.y += v.y; s.z += v.z; s.w += v.w;
    }
    red[el][pg] = s;
    __syncthreads();

    if (pg == 0) {
        const int col = (idx & (DMODEL / 4 - 1)) * 4;
        const float* bp = bkv + DMODEL + col;
        float4 acc = make_float4(__ldg(bp), __ldg(bp + 1), __ldg(bp + 2), __ldg(bp + 3));
#pragma unroll
        for (int q = 0; q < 4; q++) {
            const float4 v = red[el][q];
            acc.x += v.x; acc.y += v.y; acc.z += v.z; acc.w += v.w;
        }
        ((float4*)g_V)[idx] = acc;
    }
}

// ---------------------------------------------------------------------------
// Fused stage-2 reduce + bias + broadcast (out[b,l,:] = z[b*64 + (l>>8), :]).
// Grid (128, 8): 32 output rows per block for higher occupancy/MLP.
// ---------------------------------------------------------------------------
__global__ __launch_bounds__(256)
void reduce_broadcast(const float* __restrict__ bo, float* __restrict__ out)
{
    const int gg  = blockIdx.x;     // 0..127 : (b*64 + m)
    const int rc  = blockIdx.y;     // 0..7   : 32-row chunk
    const int t   = threadIdx.x;
    const int idx = gg * (DMODEL / 4) + t;

    const float* bp = bo + t * 4;
    float4 s = make_float4(__ldg(bp), __ldg(bp + 1), __ldg(bp + 2), __ldg(bp + 3));

    const float4* pp = (const float4*)g_P + idx;
#pragma unroll
    for (int p = 0; p < KSPLIT; p++) {
        const float4 v = pp[(size_t)p * (ROWS * DMODEL / 4)];
        s.x += v.x; s.y += v.y; s.z += v.z; s.w += v.w;
    }

    float4* op = (float4*)out + ((size_t)gg * TPF + (size_t)rc * 32) * (DMODEL / 4) + t;
#pragma unroll
    for (int r = 0; r < 32; r++)
        op[(size_t)r * (DMODEL / 4)] = s;
}

// ---------------------------------------------------------------------------
// Inputs (metadata order): 0:x 1:context 2:Wq 3:bq 4:Wkv 5:bkv 6:Wo 7:bo
// x, Wq, bq are DEAD in the reference (q is never used).
// ---------------------------------------------------------------------------
extern "C" void kernel_launch(void* const* d_in, const int* in_sizes, int n_in,
                              void* d_out, int out_size)
{
    (void)in_sizes; (void)n_in; (void)out_size;

    const float* context = (const float*)d_in[1];
    const float* Wkv     = (const float*)d_in[4];
    const float* bkv     = (const float*)d_in[5];
    const float* Wo      = (const float*)d_in[6];
    const float* bo      = (const float*)d_in[7];
    float* out           = (float*)d_out;

    static bool attr_set = false;
    if (!attr_set) {
        cudaFuncSetAttribute(gemm_tc, cudaFuncAttributeMaxDynamicSharedMemorySize, SMEM_TOTAL);
        attr_set = true;
    }

    dim3 ggrid(NTILE, KSPLIT);

    // Stage 1: v = context @ Wkv[:, 1024:2048] + bkv[1024:]
    gemm_tc<<<ggrid, 256, SMEM_TOTAL>>>(context, Wkv, 2 * DMODEL, DMODEL);
    reduce_v<<<ROWS * DMODEL / 4 / 64, 256>>>(bkv);

    // Stage 2: z-partials = v @ Wo
    gemm_tc<<<ggrid, 256, SMEM_TOTAL>>>(nullptr, Wo, DMODEL, 0);

    // Stage 3: fused reduce + bias + broadcast to the 134 MB output
    reduce_broadcast<<<dim3(ROWS, TPF / 32), 256>>>(bo, out);
}